// round 16
// baseline (speedup 1.0000x reference)
#include <cuda_runtime.h>
#include <cuda_bf16.h>
#include <cstdint>

#define BATCH 2
#define NPTS  16384
#define KNN   24
#define DM    128
#define NP    (BATCH*NPTS)
#define NR    (NP*KNN)
#define RES_ELEMS (NP*DM)
#define NT    (NR/128)          /* 6144 tiles of 128 rows */
#define NTF   (NP/64)           /* 512 tiles of 64 rows for fc kernels */

typedef unsigned long long u64;
typedef unsigned int       u32;

/* ===================== generic-PTX MMA helpers ========================== */
__device__ __forceinline__ u32 smem_u32(const void* p){
    u32 a; asm("{ .reg .u64 t; cvta.to.shared.u64 t, %1; cvt.u32.u64 %0, t; }"
               : "=r"(a) : "l"(p));
    return a;
}
__device__ __forceinline__ void ldmA(u32* a, u32 addr){
    asm volatile("ldmatrix.sync.aligned.m8n8.x4.shared.b16 {%0,%1,%2,%3}, [%4];"
        : "=r"(a[0]), "=r"(a[1]), "=r"(a[2]), "=r"(a[3]) : "r"(addr));
}
__device__ __forceinline__ void ldmB4(u32* b, u32 addr){
    asm volatile("ldmatrix.sync.aligned.m8n8.x4.shared.b16 {%0,%1,%2,%3}, [%4];"
        : "=r"(b[0]), "=r"(b[1]), "=r"(b[2]), "=r"(b[3]) : "r"(addr));
}
__device__ __forceinline__ void mma16816(float* c, const u32* a, const u32* b){
    asm volatile("mma.sync.aligned.m16n8k16.row.col.f32.bf16.bf16.f32 "
        "{%0,%1,%2,%3}, {%4,%5,%6,%7}, {%8,%9}, {%0,%1,%2,%3};"
        : "+f"(c[0]), "+f"(c[1]), "+f"(c[2]), "+f"(c[3])
        : "r"(a[0]), "r"(a[1]), "r"(a[2]), "r"(a[3]), "r"(b[0]), "r"(b[1]));
}

/* pack two fp32 into bf16x2 word: single sm_90+ instruction, RN rounding */
__device__ __forceinline__ u32 pk(float a, float b){
    u32 r; asm("cvt.rn.bf16x2.f32 %0, %1, %2;" : "=r"(r) : "f"(b), "f"(a));
    return r;
}
__device__ __forceinline__ float bf_lo(u32 w){
    return __bfloat162float(__ushort_as_bfloat16((unsigned short)(w & 0xFFFF)));
}
__device__ __forceinline__ float bf_hi(u32 w){
    return __bfloat162float(__ushort_as_bfloat16((unsigned short)(w >> 16)));
}

/* Taylor sin/cos for |x| <= ~1.2 (abs err < 1e-5, far under bf16 quantum) */
__device__ __forceinline__ float sinp(float a, float x2){
    float p = fmaf(x2, -1.984126984e-4f, 8.333333333e-3f);
    p = fmaf(x2, p, -1.666666667e-1f);
    return fmaf(a*x2, p, a);
}
__device__ __forceinline__ float cosp(float x2){
    float p = fmaf(x2, 2.480158730e-5f, -1.388888889e-3f);
    p = fmaf(x2, p, 4.166666667e-2f);
    p = fmaf(x2, p, -0.5f);
    return fmaf(x2, p, 1.0f);
}

/* weight [K x 128] row-major -> Bsm[n][k] bf16 hi/lo, row stride `stride` */
__device__ __forceinline__ void load_wt(const float* __restrict__ w, int K, int stride,
                                        char* bh, char* bl, int tid)
{
    for (int i = tid; i < K*128; i += 256) {
        int k = i >> 7, n = i & 127;
        float v = w[i];
        __nv_bfloat16 vh = __float2bfloat16(v);
        float vl = v - __bfloat162float(vh);
        int off = (n*stride + k)*2;
        *(__nv_bfloat16*)(bh + off) = vh;
        *(__nv_bfloat16*)(bl + off) = __float2bfloat16(vl);
    }
}
/* weight [K x 128] row-major -> Bsm[n][k] bf16 hi only */
__device__ __forceinline__ void load_wt_hi(const float* __restrict__ w, int K, int stride,
                                           char* bh, int tid)
{
    for (int i = tid; i < K*128; i += 256) {
        int k = i >> 7, n = i & 127;
        int off = (n*stride + k)*2;
        *(__nv_bfloat16*)(bh + off) = __float2bfloat16(w[i]);
    }
}

/* 1-pass warp GEMM: C = A*B^T, pure bf16. Warp tile (MF*16) x 64. */
template<int MF, int KSTEPS, int AST, int BST>
__device__ __forceinline__ void wgemm1(u32 aH, u32 bH,
                                       int m0, int n0, int lane,
                                       float (&C)[MF][8][4])
{
#pragma unroll
    for (int i = 0; i < MF; i++)
#pragma unroll
        for (int j = 0; j < 8; j++)
#pragma unroll
            for (int k = 0; k < 4; k++) C[i][j][k] = 0.0f;
    int arow = lane & 15, ach = lane >> 4;
    int brow4 = ((lane >> 4) & 1)*8 + (lane & 7);
    int bk4   = ((lane >> 3) & 1)*8;
#pragma unroll
    for (int ks = 0; ks < KSTEPS; ks++) {
        u32 Ah[MF][4];
#pragma unroll
        for (int mf = 0; mf < MF; mf++) {
            u32 off = (u32)(((m0 + mf*16 + arow)*AST + ks*16 + ach*8)*2);
            ldmA(Ah[mf], aH + off);
        }
        u32 Bh[8][2];
#pragma unroll
        for (int nfp = 0; nfp < 4; nfp++) {
            u32 off = (u32)(((n0 + nfp*16 + brow4)*BST + ks*16 + bk4)*2);
            ldmB4(&Bh[nfp*2][0], bH + off);
        }
#pragma unroll
        for (int nf = 0; nf < 8; nf++)
#pragma unroll
            for (int mf = 0; mf < MF; mf++)
                mma16816(C[mf][nf], Ah[mf], Bh[nf]);
    }
}

/* 3-pass warp GEMM: C = A*B^T, A split, B split: Ah*Bh + Ah*Bl + Al*Bh */
template<int MF, int KSTEPS, int AST, int BST>
__device__ __forceinline__ void wgemm3(u32 aH, u32 aL, u32 bH, u32 bL,
                                       int m0, int n0, int lane,
                                       float (&C)[MF][8][4])
{
#pragma unroll
    for (int i = 0; i < MF; i++)
#pragma unroll
        for (int j = 0; j < 8; j++)
#pragma unroll
            for (int k = 0; k < 4; k++) C[i][j][k] = 0.0f;
    int arow = lane & 15, ach = lane >> 4;
    int brow4 = ((lane >> 4) & 1)*8 + (lane & 7);
    int bk4   = ((lane >> 3) & 1)*8;
#pragma unroll
    for (int ks = 0; ks < KSTEPS; ks++) {
        u32 Ah[MF][4], Al[MF][4];
#pragma unroll
        for (int mf = 0; mf < MF; mf++) {
            u32 off = (u32)(((m0 + mf*16 + arow)*AST + ks*16 + ach*8)*2);
            ldmA(Ah[mf], aH + off);
            ldmA(Al[mf], aL + off);
        }
        u32 Bh[8][2], Bl[8][2];
#pragma unroll
        for (int nfp = 0; nfp < 4; nfp++) {
            u32 off = (u32)(((n0 + nfp*16 + brow4)*BST + ks*16 + bk4)*2);
            ldmB4(&Bh[nfp*2][0], bH + off);
            ldmB4(&Bl[nfp*2][0], bL + off);
        }
#pragma unroll
        for (int nf = 0; nf < 8; nf++)
#pragma unroll
            for (int mf = 0; mf < MF; mf++) {
                mma16816(C[mf][nf], Ah[mf], Bh[nf]);
                mma16816(C[mf][nf], Ah[mf], Bl[nf]);
                mma16816(C[mf][nf], Al[mf], Bh[nf]);
            }
    }
}

/* ---- scratch ---- */
__device__ float d_x  [NP*DM];
__device__ u32   d_xh [NP*64];             /* x as bf16x2 (for gather) */
__device__ u32   d_pe [(size_t)NR*64];     /* pe as bf16x2          */
__device__ u32   d_lgp[(size_t)NR*64];     /* logits as bf16x2      */
__device__ float d_r  [NP*DM];

__constant__ float c_omega[10] = {
  1.0f, 0.398107170553497250f, 0.158489319246111348f, 0.063095734448019331f,
  0.025118864315095794f, 0.01f, 0.003981071705534973f, 0.001584893192461114f,
  0.000630957344480193f, 0.000251188643150958f };

/* ======================= smem layout offsets ============================ */
#define F1_AH 0
#define F1_AL 9216
#define F1_BH 18432
#define F1_BL 36864
#define F1_B  55296
#define F1_SZ 55808

#define F2_AH 0
#define F2_AL 17408
#define F2_BH 34816
#define F2_BL 69632
#define F2_B  104448
#define F2_SZ 104960

#define K2_D1H 0        /* 128x72  bf16 = 18432 */
#define K2_D2H 18432    /* 128x136 bf16 = 34816 */
#define K2_G1H 53248
#define K2_G2H 88064
#define K2_EH  122880   /* E: 128 x 144B        */
#define K2_TH  141312   /* t1/h/t: 128 x 272B   */
#define K2_B1  176128
#define K2_B2  176640
#define K2_B3  177152
#define K2_B4  177664
#define K2_XG  178176   /* gathered x[gi] bf16: 128 x 272B = 34816 */
#define K2_SZ  212992

/* =========================================================================
 * K1 (HMMA): x = features @ fc1_w + fc1_b, 3-pass split-bf16.
 * 64-row tiles, warp tile 16x64. Also emits d_xh (bf16 copy of x).
 * ========================================================================= */
__global__ void __launch_bounds__(256, 1)
k_fc1m(const float* __restrict__ feat,
       const float* __restrict__ w, const float* __restrict__ bias)
{
    extern __shared__ __align__(128) char smem[];
    int tid = threadIdx.x, lane = tid & 31, wp = tid >> 5;
    int m0 = (wp >> 1) * 16, n0 = (wp & 1) * 64;
    float* bs = (float*)(smem + F1_B);

    load_wt(w, 64, 72, smem + F1_BH, smem + F1_BL, tid);
    if (tid < 128) bs[tid] = bias[tid];

    int r0 = blockIdx.x * 64;
    for (int i = tid; i < 64*64; i += 256) {
        int r = i >> 6, k = i & 63;
        float v = feat[(size_t)(r0 + r)*64 + k];
        __nv_bfloat16 vh = __float2bfloat16(v);
        *(unsigned short*)(smem + F1_AH + (r*72 + k)*2) = __bfloat16_as_ushort(vh);
        *(unsigned short*)(smem + F1_AL + (r*72 + k)*2) =
            __bfloat16_as_ushort(__float2bfloat16(v - __bfloat162float(vh)));
    }
    __syncthreads();

    float C[1][8][4];
    wgemm3<1, 4, 72, 72>(smem_u32(smem + F1_AH), smem_u32(smem + F1_AL),
                         smem_u32(smem + F1_BH), smem_u32(smem + F1_BL),
                         m0, n0, lane, C);
    int rA = m0 + (lane >> 2);
    float* oA = d_x + (size_t)(r0 + rA)*128;
    float* oB = d_x + (size_t)(r0 + rA + 8)*128;
    u32* xhA = d_xh + (size_t)(r0 + rA)*64;
    u32* xhB = d_xh + (size_t)(r0 + rA + 8)*64;
#pragma unroll
    for (int nf = 0; nf < 8; nf++) {
        int c = n0 + nf*8 + (lane & 3)*2;
        float ba = bs[c], bb = bs[c+1];
        float v0 = C[0][nf][0] + ba, v1 = C[0][nf][1] + bb;
        float v2 = C[0][nf][2] + ba, v3 = C[0][nf][3] + bb;
        *(float2*)(oA + c) = make_float2(v0, v1);
        *(float2*)(oB + c) = make_float2(v2, v3);
        xhA[c >> 1] = pk(v0, v1);
        xhB[c >> 1] = pk(v2, v3);
    }
}

/* =========================================================================
 * K2 (fused): per 128-row tile:
 *   [idx loads] embed(poly) -> G1(relu) -> [cp.async gather x[gi] bf16]
 *   -> G2 -> pe(bf16 out) + h(smem, using gathered rows)
 *   -> G3(relu) -> G4 -> logits(bf16 out).   1 CTA/SM, 208 KB smem.
 * ========================================================================= */
__global__ void __launch_bounds__(256, 1)
k2(const float* __restrict__ xyz, const int* __restrict__ knn_idx,
   const float* __restrict__ kxyz,
   const float* __restrict__ d1w, const float* __restrict__ d1b,
   const float* __restrict__ d2w, const float* __restrict__ d2b,
   const float* __restrict__ g1w, const float* __restrict__ g1b,
   const float* __restrict__ g2w, const float* __restrict__ g2b)
{
    extern __shared__ __align__(128) char smem[];
    int tid = threadIdx.x, lane = tid & 31, wp = tid >> 5;
    int m0 = (wp >> 1) * 32, n0 = (wp & 1) * 64;
    float* b1s = (float*)(smem + K2_B1);
    float* b2s = (float*)(smem + K2_B2);
    float* b3s = (float*)(smem + K2_B3);
    float* b4s = (float*)(smem + K2_B4);
    u32* xgs = (u32*)(smem + K2_XG);           /* [128][68] u32 */

    load_wt_hi(d1w, 60, 72, smem + K2_D1H, tid);
    for (int i = tid; i < 128*4; i += 256) {
        int n = i >> 2, k = 60 + (i & 3);
        *(__nv_bfloat16*)(smem + K2_D1H + (n*72 + k)*2) = __float2bfloat16(0.0f);
    }
    load_wt_hi(d2w, 128, 136, smem + K2_D2H, tid);
    load_wt_hi(g1w, 128, 136, smem + K2_G1H, tid);
    load_wt_hi(g2w, 128, 136, smem + K2_G2H, tid);
    if (tid < 128) {
        b1s[tid] = d1b[tid]; b2s[tid] = d2b[tid];
        b3s[tid] = g1b[tid]; b4s[tid] = g2b[tid];
    }
    __syncthreads();

    u32 EH  = smem_u32(smem + K2_EH);
    u32 TH  = smem_u32(smem + K2_TH);
    u32 D1H = smem_u32(smem + K2_D1H);
    u32 D2H = smem_u32(smem + K2_D2H);
    u32 G1H = smem_u32(smem + K2_G1H);
    u32 G2H = smem_u32(smem + K2_G2H);

    int er = tid & 127, eh = tid >> 7;   /* embed: row, sin/cos half  */
    int gr = tid >> 1, gc = tid & 1;     /* gather: row, 128B half    */
    u32 gdst = smem_u32(smem + K2_XG) + (u32)(gr*272 + gc*128);

    for (int tile = blockIdx.x; tile < NT; tile += gridDim.x) {
        /* ---- gather index for this thread's row (in flight thru embed) */
        int grow_g = tile*128 + gr;
        int gi = (((grow_g / KNN) >> 14) << 14) + knn_idx[grow_g];
        const u32* gsrc = d_xh + (size_t)gi*64 + gc*32;

        /* ---- embedding: MUFU for j=0,1; Taylor poly for j=2..9 ---- */
        {
            int grow = tile*128 + er;
            int p = grow / KNN;
            int qb0 = eh ? 5 : 0;
#pragma unroll
            for (int c = 0; c < 3; c++) {
                float g = xyz[p*3 + c] - kxyz[(size_t)grow*3 + c];
                float a1 = g * c_omega[1];
                u32 w0 = eh ? pk(__cosf(g), __cosf(a1))
                            : pk(__sinf(g), __sinf(a1));
                *(u32*)(smem + K2_EH + er*144 + 4*(c*10 + qb0)) = w0;
#pragma unroll
                for (int jq = 1; jq < 5; jq++) {
                    float x0 = g * c_omega[2*jq], x1 = g * c_omega[2*jq+1];
                    float s0 = x0*x0, s1 = x1*x1;
                    u32 wv = eh ? pk(cosp(s0), cosp(s1))
                                : pk(sinp(x0, s0), sinp(x1, s1));
                    *(u32*)(smem + K2_EH + er*144 + 4*(c*10 + qb0 + jq)) = wv;
                }
            }
            if (eh == 0) {
                *(u32*)(smem + K2_EH + er*144 + 4*30) = 0u;
                *(u32*)(smem + K2_EH + er*144 + 4*31) = 0u;
            }
        }
        __syncthreads();                       /* E ready */

        float C[2][8][4];
        /* ---- G1: t1 = relu(e @ d1 + b1) -> TH ---- */
        wgemm1<2, 4, 72, 72>(EH, D1H, m0, n0, lane, C);
#pragma unroll
        for (int mf = 0; mf < 2; mf++) {
            int r1 = m0 + mf*16 + (lane >> 2);
#pragma unroll
            for (int nf = 0; nf < 8; nf++) {
                int c = n0 + nf*8 + (lane & 3)*2;
                float ba = b1s[c], bb = b1s[c+1];
                *(u32*)(smem + K2_TH + r1*272 + 2*c) =
                    pk(fmaxf(C[mf][nf][0] + ba, 0.0f), fmaxf(C[mf][nf][1] + bb, 0.0f));
                *(u32*)(smem + K2_TH + (r1+8)*272 + 2*c) =
                    pk(fmaxf(C[mf][nf][2] + ba, 0.0f), fmaxf(C[mf][nf][3] + bb, 0.0f));
            }
        }
        /* ---- launch async gather of x[gi] rows (bf16) into XG ---- */
#pragma unroll
        for (int ch = 0; ch < 8; ch++) {
            asm volatile("cp.async.ca.shared.global [%0], [%1], 16;"
                         :: "r"(gdst + ch*16), "l"(gsrc + ch*4) : "memory");
        }
        asm volatile("cp.async.commit_group;" ::: "memory");
        __syncthreads();                       /* t1 ready */

        /* ---- G2: pe = t1 @ d2 + b2 ---- */
        wgemm1<2, 8, 136, 136>(TH, D2H, m0, n0, lane, C);
        asm volatile("cp.async.wait_group 0;" ::: "memory");
        __syncthreads();                       /* t1 reads done, XG ready */

        /* ---- ep2: pe -> gmem (bf16), h = x[p]-x[gi]+pe -> TH ---- */
#pragma unroll
        for (int mf = 0; mf < 2; mf++) {
            int rA = m0 + mf*16 + (lane >> 2), rB = rA + 8;
            int gA = tile*128 + rA, gB = tile*128 + rB;
            int pA = gA / KNN, pB = gB / KNN;
            const float* xpA = d_x + (size_t)pA*128;
            const float* xpB = d_x + (size_t)pB*128;
            u32* peA = d_pe + (size_t)gA*64;
            u32* peB = d_pe + (size_t)gB*64;
#pragma unroll
            for (int nf = 0; nf < 8; nf++) {
                int c = n0 + nf*8 + (lane & 3)*2;
                int cw = c >> 1;
                float ba = b2s[c], bb = b2s[c+1];
                float2 xa = *(const float2*)(xpA + c);
                float2 xb = *(const float2*)(xpB + c);
                u32 ga = xgs[rA*68 + cw];
                u32 gb = xgs[rB*68 + cw];
                float p0 = C[mf][nf][0] + ba, p1 = C[mf][nf][1] + bb;
                peA[cw] = pk(p0, p1);
                *(u32*)(smem + K2_TH + rA*272 + 2*c) =
                    pk(xa.x - bf_lo(ga) + p0, xa.y - bf_hi(ga) + p1);
                float p2 = C[mf][nf][2] + ba, p3 = C[mf][nf][3] + bb;
                peB[cw] = pk(p2, p3);
                *(u32*)(smem + K2_TH + rB*272 + 2*c) =
                    pk(xb.x - bf_lo(gb) + p2, xb.y - bf_hi(gb) + p3);
            }
        }
        __syncthreads();                       /* h ready */

        /* ---- G3: t = relu(h @ g1 + b3) ---- */
        wgemm1<2, 8, 136, 136>(TH, G1H, m0, n0, lane, C);
        __syncthreads();                       /* all h reads done */
#pragma unroll
        for (int mf = 0; mf < 2; mf++) {
            int r1 = m0 + mf*16 + (lane >> 2);
#pragma unroll
            for (int nf = 0; nf < 8; nf++) {
                int c = n0 + nf*8 + (lane & 3)*2;
                float ba = b3s[c], bb = b3s[c+1];
                *(u32*)(smem + K2_TH + r1*272 + 2*c) =
                    pk(fmaxf(C[mf][nf][0] + ba, 0.0f), fmaxf(C[mf][nf][1] + bb, 0.0f));
                *(u32*)(smem + K2_TH + (r1+8)*272 + 2*c) =
                    pk(fmaxf(C[mf][nf][2] + ba, 0.0f), fmaxf(C[mf][nf][3] + bb, 0.0f));
            }
        }
        __syncthreads();                       /* t ready */

        /* ---- G4: logits = t @ g2 + b4 -> bf16x2 gmem ---- */
        wgemm1<2, 8, 136, 136>(TH, G2H, m0, n0, lane, C);
#pragma unroll
        for (int mf = 0; mf < 2; mf++) {
            int rA = m0 + mf*16 + (lane >> 2), rB = rA + 8;
            u32* lgA = d_lgp + (size_t)(tile*128 + rA)*64;
            u32* lgB = d_lgp + (size_t)(tile*128 + rB)*64;
#pragma unroll
            for (int nf = 0; nf < 8; nf++) {
                int c = n0 + nf*8 + (lane & 3)*2;
                float ba = b4s[c], bb = b4s[c+1];
                lgA[c >> 1] = pk(C[mf][nf][0] + ba, C[mf][nf][1] + bb);
                lgB[c >> 1] = pk(C[mf][nf][2] + ba, C[mf][nf][3] + bb);
            }
        }
        /* next write to TH happens after the embed __syncthreads */
    }
}

/* =========================================================================
 * K3: softmax over k + aggregate. block = point p, thread = channel f.
 * ========================================================================= */
__global__ void k_soft(const int* __restrict__ knn_idx,
                       float* __restrict__ out_attn)
{
    int p = blockIdx.x, f = threadIdx.x;
    int base = p * KNN, bb = p >> 14;
    const float scale = 0.0883883476483184406f;   /* 1/sqrt(128) */
    float acc[KNN];
    float m = -1e30f;
#pragma unroll
    for (int k = 0; k < KNN; k++) {
        u32 wv = d_lgp[(size_t)(base + k)*64 + (f >> 1)];
        acc[k] = ((f & 1) ? bf_hi(wv) : bf_lo(wv)) * scale;
        m = fmaxf(m, acc[k]);
    }
    float s = 0.0f;
#pragma unroll
    for (int k = 0; k < KNN; k++) { acc[k] = __expf(acc[k] - m); s += acc[k]; }
    float inv = 1.0f / s;
    float rv = 0.0f;
#pragma unroll
    for (int k = 0; k < KNN; k++) {
        float a = acc[k] * inv;
        int grow = base + k;
        out_attn[(size_t)grow*128 + f] = a;
        int gi = (bb << 14) + knn_idx[grow];
        u32 pw = d_pe[(size_t)grow*64 + (f >> 1)];
        float pe = (f & 1) ? bf_hi(pw) : bf_lo(pw);
        rv = fmaf(a, d_x[(size_t)gi*128 + f] + pe, rv);
    }
    d_r[p*128 + f] = rv;
}

/* =========================================================================
 * K4 (HMMA): res = r @ fc2 + fc2_b + x, 3-pass split-bf16.
 * 64-row tiles, warp tile 16x64.
 * ========================================================================= */
__global__ void __launch_bounds__(256, 1)
k_fc2m(const float* __restrict__ w, const float* __restrict__ bias,
       float* __restrict__ out_res)
{
    extern __shared__ __align__(128) char smem[];
    int tid = threadIdx.x, lane = tid & 31, wp = tid >> 5;
    int m0 = (wp >> 1) * 16, n0 = (wp & 1) * 64;
    float* bs = (float*)(smem + F2_B);

    load_wt(w, 128, 136, smem + F2_BH, smem + F2_BL, tid);
    if (tid < 128) bs[tid] = bias[tid];

    int r0 = blockIdx.x * 64;
    for (int i = tid; i < 64*128; i += 256) {
        int r = i >> 7, k = i & 127;
        float v = d_r[(size_t)(r0 + r)*128 + k];
        __nv_bfloat16 vh = __float2bfloat16(v);
        *(unsigned short*)(smem + F2_AH + (r*136 + k)*2) = __bfloat16_as_ushort(vh);
        *(unsigned short*)(smem + F2_AL + (r*136 + k)*2) =
            __bfloat16_as_ushort(__float2bfloat16(v - __bfloat162float(vh)));
    }
    __syncthreads();

    float C[1][8][4];
    wgemm3<1, 8, 136, 136>(smem_u32(smem + F2_AH), smem_u32(smem + F2_AL),
                           smem_u32(smem + F2_BH), smem_u32(smem + F2_BL),
                           m0, n0, lane, C);
    int rA = m0 + (lane >> 2);
    const float* xA = d_x + (size_t)(r0 + rA)*128;
    const float* xB = d_x + (size_t)(r0 + rA + 8)*128;
    float* oA = out_res + (size_t)(r0 + rA)*128;
    float* oB = out_res + (size_t)(r0 + rA + 8)*128;
#pragma unroll
    for (int nf = 0; nf < 8; nf++) {
        int c = n0 + nf*8 + (lane & 3)*2;
        float ba = bs[c], bb = bs[c+1];
        float2 xa = *(const float2*)(xA + c);
        float2 xb = *(const float2*)(xB + c);
        *(float2*)(oA + c) = make_float2(C[0][nf][0] + ba + xa.x,
                                         C[0][nf][1] + bb + xa.y);
        *(float2*)(oB + c) = make_float2(C[0][nf][2] + ba + xb.x,
                                         C[0][nf][3] + bb + xb.y);
    }
}

/* ========================================================================= */
extern "C" void kernel_launch(void* const* d_in, const int* in_sizes, int n_in,
                              void* d_out, int out_size)
{
    const float* feat = (const float*)d_in[0];
    const float* xyz  = (const float*)d_in[1];
    const int*   knn  = (const int*  )d_in[2];
    const float* kxyz = (const float*)d_in[3];
    const float* fc1w = (const float*)d_in[4];
    const float* fc1b = (const float*)d_in[5];
    const float* fc2w = (const float*)d_in[6];
    const float* fc2b = (const float*)d_in[7];
    const float* d1w  = (const float*)d_in[8];
    const float* d1b  = (const float*)d_in[9];
    const float* d2w  = (const float*)d_in[10];
    const float* d2b  = (const float*)d_in[11];
    const float* g1w  = (const float*)d_in[12];
    const float* g1b  = (const float*)d_in[13];
    const float* g2w  = (const float*)d_in[14];
    const float* g2b  = (const float*)d_in[15];
    float* out = (float*)d_out;

    int sms = 148;
    cudaDeviceGetAttribute(&sms, cudaDevAttrMultiProcessorCount, 0);

    cudaFuncSetAttribute(k_fc1m, cudaFuncAttributeMaxDynamicSharedMemorySize, F1_SZ);
    cudaFuncSetAttribute(k2,     cudaFuncAttributeMaxDynamicSharedMemorySize, K2_SZ);
    cudaFuncSetAttribute(k_fc2m, cudaFuncAttributeMaxDynamicSharedMemorySize, F2_SZ);

    k_fc1m<<<NTF, 256, F1_SZ>>>(feat, fc1w, fc1b);
    k2    <<<sms, 256, K2_SZ>>>(xyz, knn, kxyz, d1w, d1b, d2w, d2b,
                                g1w, g1b, g2w, g2b);
    k_soft<<<NP,  128       >>>(knn, out + RES_ELEMS);
    k_fc2m<<<NTF, 256, F2_SZ>>>(fc2w, fc2b, out);
}

// round 17
// speedup vs baseline: 1.0280x; 1.0280x over previous
#include <cuda_runtime.h>
#include <cuda_bf16.h>
#include <cstdint>

#define BATCH 2
#define NPTS  16384
#define KNN   24
#define DM    128
#define NP    (BATCH*NPTS)
#define NR    (NP*KNN)
#define RES_ELEMS (NP*DM)
#define NT    (NR/128)          /* 6144 tiles of 128 rows */
#define NTF   (NP/64)           /* 512 tiles of 64 rows for fc kernels */

typedef unsigned long long u64;
typedef unsigned int       u32;

/* ===================== generic-PTX MMA helpers ========================== */
__device__ __forceinline__ u32 smem_u32(const void* p){
    u32 a; asm("{ .reg .u64 t; cvta.to.shared.u64 t, %1; cvt.u32.u64 %0, t; }"
               : "=r"(a) : "l"(p));
    return a;
}
__device__ __forceinline__ void ldmA(u32* a, u32 addr){
    asm volatile("ldmatrix.sync.aligned.m8n8.x4.shared.b16 {%0,%1,%2,%3}, [%4];"
        : "=r"(a[0]), "=r"(a[1]), "=r"(a[2]), "=r"(a[3]) : "r"(addr));
}
__device__ __forceinline__ void ldmB4(u32* b, u32 addr){
    asm volatile("ldmatrix.sync.aligned.m8n8.x4.shared.b16 {%0,%1,%2,%3}, [%4];"
        : "=r"(b[0]), "=r"(b[1]), "=r"(b[2]), "=r"(b[3]) : "r"(addr));
}
__device__ __forceinline__ void mma16816(float* c, const u32* a, const u32* b){
    asm volatile("mma.sync.aligned.m16n8k16.row.col.f32.bf16.bf16.f32 "
        "{%0,%1,%2,%3}, {%4,%5,%6,%7}, {%8,%9}, {%0,%1,%2,%3};"
        : "+f"(c[0]), "+f"(c[1]), "+f"(c[2]), "+f"(c[3])
        : "r"(a[0]), "r"(a[1]), "r"(a[2]), "r"(a[3]), "r"(b[0]), "r"(b[1]));
}

/* pack two fp32 into bf16x2 word: single sm_90+ instruction, RN rounding */
__device__ __forceinline__ u32 pk(float a, float b){
    u32 r; asm("cvt.rn.bf16x2.f32 %0, %1, %2;" : "=r"(r) : "f"(b), "f"(a));
    return r;
}
__device__ __forceinline__ float bf_lo(u32 w){
    return __bfloat162float(__ushort_as_bfloat16((unsigned short)(w & 0xFFFF)));
}
__device__ __forceinline__ float bf_hi(u32 w){
    return __bfloat162float(__ushort_as_bfloat16((unsigned short)(w >> 16)));
}

/* Taylor sin/cos for |x| <= ~1.2 (abs err < 1e-5, far under bf16 quantum) */
__device__ __forceinline__ float sinp(float a, float x2){
    float p = fmaf(x2, -1.984126984e-4f, 8.333333333e-3f);
    p = fmaf(x2, p, -1.666666667e-1f);
    return fmaf(a*x2, p, a);
}
__device__ __forceinline__ float cosp(float x2){
    float p = fmaf(x2, 2.480158730e-5f, -1.388888889e-3f);
    p = fmaf(x2, p, 4.166666667e-2f);
    p = fmaf(x2, p, -0.5f);
    return fmaf(x2, p, 1.0f);
}

/* weight [K x 128] row-major -> Bsm[n][k] bf16 hi/lo, row stride `stride` */
__device__ __forceinline__ void load_wt(const float* __restrict__ w, int K, int stride,
                                        char* bh, char* bl, int tid)
{
    for (int i = tid; i < K*128; i += 256) {
        int k = i >> 7, n = i & 127;
        float v = w[i];
        __nv_bfloat16 vh = __float2bfloat16(v);
        float vl = v - __bfloat162float(vh);
        int off = (n*stride + k)*2;
        *(__nv_bfloat16*)(bh + off) = vh;
        *(__nv_bfloat16*)(bl + off) = __float2bfloat16(vl);
    }
}
/* weight [K x 128] row-major -> Bsm[n][k] bf16 hi only */
__device__ __forceinline__ void load_wt_hi(const float* __restrict__ w, int K, int stride,
                                           char* bh, int tid)
{
    for (int i = tid; i < K*128; i += 256) {
        int k = i >> 7, n = i & 127;
        int off = (n*stride + k)*2;
        *(__nv_bfloat16*)(bh + off) = __float2bfloat16(w[i]);
    }
}

/* 1-pass warp GEMM: C = A*B^T, pure bf16. Warp tile (MF*16) x 64. */
template<int MF, int KSTEPS, int AST, int BST>
__device__ __forceinline__ void wgemm1(u32 aH, u32 bH,
                                       int m0, int n0, int lane,
                                       float (&C)[MF][8][4])
{
#pragma unroll
    for (int i = 0; i < MF; i++)
#pragma unroll
        for (int j = 0; j < 8; j++)
#pragma unroll
            for (int k = 0; k < 4; k++) C[i][j][k] = 0.0f;
    int arow = lane & 15, ach = lane >> 4;
    int brow4 = ((lane >> 4) & 1)*8 + (lane & 7);
    int bk4   = ((lane >> 3) & 1)*8;
#pragma unroll
    for (int ks = 0; ks < KSTEPS; ks++) {
        u32 Ah[MF][4];
#pragma unroll
        for (int mf = 0; mf < MF; mf++) {
            u32 off = (u32)(((m0 + mf*16 + arow)*AST + ks*16 + ach*8)*2);
            ldmA(Ah[mf], aH + off);
        }
        u32 Bh[8][2];
#pragma unroll
        for (int nfp = 0; nfp < 4; nfp++) {
            u32 off = (u32)(((n0 + nfp*16 + brow4)*BST + ks*16 + bk4)*2);
            ldmB4(&Bh[nfp*2][0], bH + off);
        }
#pragma unroll
        for (int nf = 0; nf < 8; nf++)
#pragma unroll
            for (int mf = 0; mf < MF; mf++)
                mma16816(C[mf][nf], Ah[mf], Bh[nf]);
    }
}

/* 3-pass warp GEMM: C = A*B^T, A split, B split: Ah*Bh + Ah*Bl + Al*Bh */
template<int MF, int KSTEPS, int AST, int BST>
__device__ __forceinline__ void wgemm3(u32 aH, u32 aL, u32 bH, u32 bL,
                                       int m0, int n0, int lane,
                                       float (&C)[MF][8][4])
{
#pragma unroll
    for (int i = 0; i < MF; i++)
#pragma unroll
        for (int j = 0; j < 8; j++)
#pragma unroll
            for (int k = 0; k < 4; k++) C[i][j][k] = 0.0f;
    int arow = lane & 15, ach = lane >> 4;
    int brow4 = ((lane >> 4) & 1)*8 + (lane & 7);
    int bk4   = ((lane >> 3) & 1)*8;
#pragma unroll
    for (int ks = 0; ks < KSTEPS; ks++) {
        u32 Ah[MF][4], Al[MF][4];
#pragma unroll
        for (int mf = 0; mf < MF; mf++) {
            u32 off = (u32)(((m0 + mf*16 + arow)*AST + ks*16 + ach*8)*2);
            ldmA(Ah[mf], aH + off);
            ldmA(Al[mf], aL + off);
        }
        u32 Bh[8][2], Bl[8][2];
#pragma unroll
        for (int nfp = 0; nfp < 4; nfp++) {
            u32 off = (u32)(((n0 + nfp*16 + brow4)*BST + ks*16 + bk4)*2);
            ldmB4(&Bh[nfp*2][0], bH + off);
            ldmB4(&Bl[nfp*2][0], bL + off);
        }
#pragma unroll
        for (int nf = 0; nf < 8; nf++)
#pragma unroll
            for (int mf = 0; mf < MF; mf++) {
                mma16816(C[mf][nf], Ah[mf], Bh[nf]);
                mma16816(C[mf][nf], Ah[mf], Bl[nf]);
                mma16816(C[mf][nf], Al[mf], Bh[nf]);
            }
    }
}

/* ---- scratch ---- */
__device__ float d_x  [NP*DM];
__device__ u32   d_pe [(size_t)NR*64];     /* pe as bf16x2          */
__device__ u32   d_hh [(size_t)NR*64];     /* h as bf16x2           */
__device__ u32   d_lgp[(size_t)NR*64];     /* logits as bf16x2      */
__device__ float d_r  [NP*DM];

__constant__ float c_omega[10] = {
  1.0f, 0.398107170553497250f, 0.158489319246111348f, 0.063095734448019331f,
  0.025118864315095794f, 0.01f, 0.003981071705534973f, 0.001584893192461114f,
  0.000630957344480193f, 0.000251188643150958f };

/* ======================= smem layout offsets ============================ */
#define F1_AH 0
#define F1_AL 9216
#define F1_BH 18432
#define F1_BL 36864
#define F1_B  55296
#define F1_SZ 55808

#define F2_AH 0
#define F2_AL 17408
#define F2_BH 34816
#define F2_BL 69632
#define F2_B  104448
#define F2_SZ 104960

#define K2A_D1H 0
#define K2A_D2H 18432
#define K2A_EH  53248
#define K2A_TH  71680
#define K2A_B1  106496
#define K2A_B2  107008
#define K2A_SZ  107520

#define K2B_G1H 0
#define K2B_G2H 34816
#define K2B_H0  69632
#define K2B_H1  104448
#define K2B_B3  139264
#define K2B_B4  139776
#define K2B_SZ  140288

/* =========================================================================
 * K1 (HMMA): x = features @ fc1_w + fc1_b, 3-pass split-bf16.
 * 64-row tiles, warp tile 16x64, 2 CTAs/SM.
 * ========================================================================= */
__global__ void __launch_bounds__(256, 2)
k_fc1m(const float* __restrict__ feat,
       const float* __restrict__ w, const float* __restrict__ bias)
{
    extern __shared__ __align__(128) char smem[];
    int tid = threadIdx.x, lane = tid & 31, wp = tid >> 5;
    int m0 = (wp >> 1) * 16, n0 = (wp & 1) * 64;
    float* bs = (float*)(smem + F1_B);

    load_wt(w, 64, 72, smem + F1_BH, smem + F1_BL, tid);
    if (tid < 128) bs[tid] = bias[tid];

    int r0 = blockIdx.x * 64;
    for (int i = tid; i < 64*64; i += 256) {
        int r = i >> 6, k = i & 63;
        float v = feat[(size_t)(r0 + r)*64 + k];
        __nv_bfloat16 vh = __float2bfloat16(v);
        *(unsigned short*)(smem + F1_AH + (r*72 + k)*2) = __bfloat16_as_ushort(vh);
        *(unsigned short*)(smem + F1_AL + (r*72 + k)*2) =
            __bfloat16_as_ushort(__float2bfloat16(v - __bfloat162float(vh)));
    }
    __syncthreads();

    float C[1][8][4];
    wgemm3<1, 4, 72, 72>(smem_u32(smem + F1_AH), smem_u32(smem + F1_AL),
                         smem_u32(smem + F1_BH), smem_u32(smem + F1_BL),
                         m0, n0, lane, C);
    int rA = m0 + (lane >> 2);
    float* oA = d_x + (size_t)(r0 + rA)*128;
    float* oB = d_x + (size_t)(r0 + rA + 8)*128;
#pragma unroll
    for (int nf = 0; nf < 8; nf++) {
        int c = n0 + nf*8 + (lane & 3)*2;
        float ba = bs[c], bb = bs[c+1];
        *(float2*)(oA + c) = make_float2(C[0][nf][0] + ba, C[0][nf][1] + bb);
        *(float2*)(oB + c) = make_float2(C[0][nf][2] + ba, C[0][nf][3] + bb);
    }
}

/* =========================================================================
 * K2a: per 128-row tile: poly-embed -> G1(relu, 1-pass) -> G2(1-pass)
 *      -> pe(bf16x2) + h(bf16x2).  2 CTAs/SM.
 * ========================================================================= */
__global__ void __launch_bounds__(256, 2)
k2a(const float* __restrict__ xyz, const int* __restrict__ knn_idx,
    const float* __restrict__ kxyz,
    const float* __restrict__ d1w, const float* __restrict__ d1b,
    const float* __restrict__ d2w, const float* __restrict__ d2b)
{
    extern __shared__ __align__(128) char smem[];
    int tid = threadIdx.x, lane = tid & 31, wp = tid >> 5;
    int m0 = (wp >> 1) * 32, n0 = (wp & 1) * 64;
    float* b1s = (float*)(smem + K2A_B1);
    float* b2s = (float*)(smem + K2A_B2);

    load_wt_hi(d1w, 60, 72, smem + K2A_D1H, tid);
    for (int i = tid; i < 128*4; i += 256) {
        int n = i >> 2, k = 60 + (i & 3);
        *(__nv_bfloat16*)(smem + K2A_D1H + (n*72 + k)*2) = __float2bfloat16(0.0f);
    }
    load_wt_hi(d2w, 128, 136, smem + K2A_D2H, tid);
    if (tid < 128) { b1s[tid] = d1b[tid]; b2s[tid] = d2b[tid]; }
    __syncthreads();

    u32 EH = smem_u32(smem + K2A_EH);
    u32 TH = smem_u32(smem + K2A_TH);
    u32 D1H = smem_u32(smem + K2A_D1H);
    u32 D2H = smem_u32(smem + K2A_D2H);

    int er = tid & 127, eh = tid >> 7;   /* embed: row, sin/cos half */

    for (int tile = blockIdx.x; tile < NT; tile += gridDim.x) {
        /* ---- embedding: MUFU for j=0,1; Taylor poly for j=2..9 ---- */
        {
            int grow = tile*128 + er;
            int p = grow / KNN;
            int qb0 = eh ? 5 : 0;
#pragma unroll
            for (int c = 0; c < 3; c++) {
                float g = xyz[p*3 + c] - kxyz[(size_t)grow*3 + c];
                float a1 = g * c_omega[1];
                u32 w0 = eh ? pk(__cosf(g), __cosf(a1))
                            : pk(__sinf(g), __sinf(a1));
                *(u32*)(smem + K2A_EH + er*144 + 4*(c*10 + qb0)) = w0;
#pragma unroll
                for (int jq = 1; jq < 5; jq++) {
                    float x0 = g * c_omega[2*jq], x1 = g * c_omega[2*jq+1];
                    float s0 = x0*x0, s1 = x1*x1;
                    u32 wv = eh ? pk(cosp(s0), cosp(s1))
                                : pk(sinp(x0, s0), sinp(x1, s1));
                    *(u32*)(smem + K2A_EH + er*144 + 4*(c*10 + qb0 + jq)) = wv;
                }
            }
            if (eh == 0) {
                *(u32*)(smem + K2A_EH + er*144 + 4*30) = 0u;
                *(u32*)(smem + K2A_EH + er*144 + 4*31) = 0u;
            }
        }
        __syncthreads();

        float C[2][8][4];
        /* ---- G1: t1 = relu(e @ d1 + b1), 1-pass ---- */
        wgemm1<2, 4, 72, 72>(EH, D1H, m0, n0, lane, C);
#pragma unroll
        for (int mf = 0; mf < 2; mf++) {
            int r1 = m0 + mf*16 + (lane >> 2);
#pragma unroll
            for (int nf = 0; nf < 8; nf++) {
                int c = n0 + nf*8 + (lane & 3)*2;
                float ba = b1s[c], bb = b1s[c+1];
                *(u32*)(smem + K2A_TH + r1*272 + 2*c) =
                    pk(fmaxf(C[mf][nf][0] + ba, 0.0f), fmaxf(C[mf][nf][1] + bb, 0.0f));
                *(u32*)(smem + K2A_TH + (r1+8)*272 + 2*c) =
                    pk(fmaxf(C[mf][nf][2] + ba, 0.0f), fmaxf(C[mf][nf][3] + bb, 0.0f));
            }
        }
        __syncthreads();

        /* ---- G2: pe = t1 @ d2 + b2, 1-pass ---- */
        wgemm1<2, 8, 136, 136>(TH, D2H, m0, n0, lane, C);
#pragma unroll
        for (int mf = 0; mf < 2; mf++) {
            int rA = m0 + mf*16 + (lane >> 2), rB = rA + 8;
            int gA = tile*128 + rA, gB = tile*128 + rB;
            int pA = gA / KNN, pB = gB / KNN;
            int iA = ((pA >> 14) << 14) + knn_idx[gA];
            int iB = ((pB >> 14) << 14) + knn_idx[gB];
            const float* xpA = d_x + (size_t)pA*128;
            const float* xgA = d_x + (size_t)iA*128;
            const float* xpB = d_x + (size_t)pB*128;
            const float* xgB = d_x + (size_t)iB*128;
            u32* peA = d_pe + (size_t)gA*64;
            u32* peB = d_pe + (size_t)gB*64;
            u32* hhA = d_hh + (size_t)gA*64;
            u32* hhB = d_hh + (size_t)gB*64;
#pragma unroll
            for (int nf = 0; nf < 8; nf++) {
                int c = n0 + nf*8 + (lane & 3)*2;
                float ba = b2s[c], bb = b2s[c+1];
                float2 xa = *(const float2*)(xpA + c), ga = *(const float2*)(xgA + c);
                float2 xb = *(const float2*)(xpB + c), gb = *(const float2*)(xgB + c);
                float p0 = C[mf][nf][0] + ba, p1 = C[mf][nf][1] + bb;
                peA[c >> 1] = pk(p0, p1);
                hhA[c >> 1] = pk(xa.x - ga.x + p0, xa.y - ga.y + p1);
                float p2 = C[mf][nf][2] + ba, p3 = C[mf][nf][3] + bb;
                peB[c >> 1] = pk(p2, p3);
                hhB[c >> 1] = pk(xb.x - gb.x + p2, xb.y - gb.y + p3);
            }
        }
        __syncthreads();
    }
}

/* ---- cp.async prefetch of one h tile (32 KB) into smem buffer ---- */
__device__ __forceinline__ void prefetch_h(char* dst, int tile, int tid)
{
    const u32* src = d_hh + (size_t)tile * 8192;
#pragma unroll
    for (int j = 0; j < 8; j++) {
        int wi = tid + j*256;                       /* 0..2047 16B chunks */
        u32 daddr = smem_u32(dst + (wi >> 4)*272 + (wi & 15)*16);
        asm volatile("cp.async.ca.shared.global [%0], [%1], 16;"
                     :: "r"(daddr), "l"(src + wi*4) : "memory");
    }
    asm volatile("cp.async.commit_group;" ::: "memory");
}

/* =========================================================================
 * K2b: per 128-row tile: h -> G3(relu, 1-pass) -> G4(1-pass) -> logits bf16
 * double-buffered cp.async h prefetch.
 * ========================================================================= */
__global__ void __launch_bounds__(256, 1)
k2b(const float* __restrict__ g1w, const float* __restrict__ g1b,
    const float* __restrict__ g2w, const float* __restrict__ g2b)
{
    extern __shared__ __align__(128) char smem[];
    int tid = threadIdx.x, lane = tid & 31, wp = tid >> 5;
    int m0 = (wp >> 1) * 32, n0 = (wp & 1) * 64;
    float* b3s = (float*)(smem + K2B_B3);
    float* b4s = (float*)(smem + K2B_B4);

    load_wt_hi(g1w, 128, 136, smem + K2B_G1H, tid);
    load_wt_hi(g2w, 128, 136, smem + K2B_G2H, tid);
    if (tid < 128) { b3s[tid] = g1b[tid]; b4s[tid] = g2b[tid]; }

    u32 G1H = smem_u32(smem + K2B_G1H);
    u32 G2H = smem_u32(smem + K2B_G2H);
    char* hbuf[2] = { smem + K2B_H0, smem + K2B_H1 };
    u32 hadr[2] = { smem_u32(smem + K2B_H0), smem_u32(smem + K2B_H1) };

    int tile = blockIdx.x;
    if (tile < NT) prefetch_h(hbuf[0], tile, tid);
    __syncthreads();
    int cur = 0;

    for (; tile < NT; tile += gridDim.x, cur ^= 1) {
        asm volatile("cp.async.wait_group 0;" ::: "memory");
        __syncthreads();
        int nxt = tile + gridDim.x;
        if (nxt < NT) prefetch_h(hbuf[cur ^ 1], nxt, tid);

        float C[2][8][4];
        /* ---- G3: t = relu(h @ g1 + b3), 1-pass ---- */
        wgemm1<2, 8, 136, 136>(hadr[cur], G1H, m0, n0, lane, C);
        __syncthreads();   /* all warps done reading h before overwrite */
#pragma unroll
        for (int mf = 0; mf < 2; mf++) {
            int r1 = m0 + mf*16 + (lane >> 2);
#pragma unroll
            for (int nf = 0; nf < 8; nf++) {
                int c = n0 + nf*8 + (lane & 3)*2;
                float ba = b3s[c], bb = b3s[c+1];
                *(u32*)(hbuf[cur] + r1*272 + 2*c) =
                    pk(fmaxf(C[mf][nf][0] + ba, 0.0f), fmaxf(C[mf][nf][1] + bb, 0.0f));
                *(u32*)(hbuf[cur] + (r1+8)*272 + 2*c) =
                    pk(fmaxf(C[mf][nf][2] + ba, 0.0f), fmaxf(C[mf][nf][3] + bb, 0.0f));
            }
        }
        __syncthreads();

        /* ---- G4: logits = t @ g2 + b4, 1-pass -> bf16x2 gmem ---- */
        wgemm1<2, 8, 136, 136>(hadr[cur], G2H, m0, n0, lane, C);
#pragma unroll
        for (int mf = 0; mf < 2; mf++) {
            int rA = m0 + mf*16 + (lane >> 2), rB = rA + 8;
            u32* lgA = d_lgp + (size_t)(tile*128 + rA)*64;
            u32* lgB = d_lgp + (size_t)(tile*128 + rB)*64;
#pragma unroll
            for (int nf = 0; nf < 8; nf++) {
                int c = n0 + nf*8 + (lane & 3)*2;
                float ba = b4s[c], bb = b4s[c+1];
                lgA[c >> 1] = pk(C[mf][nf][0] + ba, C[mf][nf][1] + bb);
                lgB[c >> 1] = pk(C[mf][nf][2] + ba, C[mf][nf][3] + bb);
            }
        }
        __syncthreads();   /* all warps done reading t before next tile reuse */
    }
}

/* =========================================================================
 * K3: softmax over k + aggregate. block = point p, thread = channel f.
 * ========================================================================= */
__global__ void k_soft(const int* __restrict__ knn_idx,
                       float* __restrict__ out_attn)
{
    int p = blockIdx.x, f = threadIdx.x;
    int base = p * KNN, bb = p >> 14;
    const float scale = 0.0883883476483184406f;   /* 1/sqrt(128) */
    float acc[KNN];
    float m = -1e30f;
#pragma unroll
    for (int k = 0; k < KNN; k++) {
        u32 wv = d_lgp[(size_t)(base + k)*64 + (f >> 1)];
        acc[k] = ((f & 1) ? bf_hi(wv) : bf_lo(wv)) * scale;
        m = fmaxf(m, acc[k]);
    }
    float s = 0.0f;
#pragma unroll
    for (int k = 0; k < KNN; k++) { acc[k] = __expf(acc[k] - m); s += acc[k]; }
    float inv = 1.0f / s;
    float rv = 0.0f;
#pragma unroll
    for (int k = 0; k < KNN; k++) {
        float a = acc[k] * inv;
        int grow = base + k;
        out_attn[(size_t)grow*128 + f] = a;
        int gi = (bb << 14) + knn_idx[grow];
        u32 pw = d_pe[(size_t)grow*64 + (f >> 1)];
        float pe = (f & 1) ? bf_hi(pw) : bf_lo(pw);
        rv = fmaf(a, d_x[(size_t)gi*128 + f] + pe, rv);
    }
    d_r[p*128 + f] = rv;
}

/* =========================================================================
 * K4 (HMMA): res = r @ fc2 + fc2_b + x, 3-pass split-bf16.
 * 64-row tiles, warp tile 16x64, 2 CTAs/SM.
 * ========================================================================= */
__global__ void __launch_bounds__(256, 2)
k_fc2m(const float* __restrict__ w, const float* __restrict__ bias,
       float* __restrict__ out_res)
{
    extern __shared__ __align__(128) char smem[];
    int tid = threadIdx.x, lane = tid & 31, wp = tid >> 5;
    int m0 = (wp >> 1) * 16, n0 = (wp & 1) * 64;
    float* bs = (float*)(smem + F2_B);

    load_wt(w, 128, 136, smem + F2_BH, smem + F2_BL, tid);
    if (tid < 128) bs[tid] = bias[tid];

    int r0 = blockIdx.x * 64;
    for (int i = tid; i < 64*128; i += 256) {
        int r = i >> 7, k = i & 127;
        float v = d_r[(size_t)(r0 + r)*128 + k];
        __nv_bfloat16 vh = __float2bfloat16(v);
        *(unsigned short*)(smem + F2_AH + (r*136 + k)*2) = __bfloat16_as_ushort(vh);
        *(unsigned short*)(smem + F2_AL + (r*136 + k)*2) =
            __bfloat16_as_ushort(__float2bfloat16(v - __bfloat162float(vh)));
    }
    __syncthreads();

    float C[1][8][4];
    wgemm3<1, 8, 136, 136>(smem_u32(smem + F2_AH), smem_u32(smem + F2_AL),
                           smem_u32(smem + F2_BH), smem_u32(smem + F2_BL),
                           m0, n0, lane, C);
    int rA = m0 + (lane >> 2);
    const float* xA = d_x + (size_t)(r0 + rA)*128;
    const float* xB = d_x + (size_t)(r0 + rA + 8)*128;
    float* oA = out_res + (size_t)(r0 + rA)*128;
    float* oB = out_res + (size_t)(r0 + rA + 8)*128;
#pragma unroll
    for (int nf = 0; nf < 8; nf++) {
        int c = n0 + nf*8 + (lane & 3)*2;
        float ba = bs[c], bb = bs[c+1];
        float2 xa = *(const float2*)(xA + c);
        float2 xb = *(const float2*)(xB + c);
        *(float2*)(oA + c) = make_float2(C[0][nf][0] + ba + xa.x,
                                         C[0][nf][1] + bb + xa.y);
        *(float2*)(oB + c) = make_float2(C[0][nf][2] + ba + xb.x,
                                         C[0][nf][3] + bb + xb.y);
    }
}

/* ========================================================================= */
extern "C" void kernel_launch(void* const* d_in, const int* in_sizes, int n_in,
                              void* d_out, int out_size)
{
    const float* feat = (const float*)d_in[0];
    const float* xyz  = (const float*)d_in[1];
    const int*   knn  = (const int*  )d_in[2];
    const float* kxyz = (const float*)d_in[3];
    const float* fc1w = (const float*)d_in[4];
    const float* fc1b = (const float*)d_in[5];
    const float* fc2w = (const float*)d_in[6];
    const float* fc2b = (const float*)d_in[7];
    const float* d1w  = (const float*)d_in[8];
    const float* d1b  = (const float*)d_in[9];
    const float* d2w  = (const float*)d_in[10];
    const float* d2b  = (const float*)d_in[11];
    const float* g1w  = (const float*)d_in[12];
    const float* g1b  = (const float*)d_in[13];
    const float* g2w  = (const float*)d_in[14];
    const float* g2b  = (const float*)d_in[15];
    float* out = (float*)d_out;

    int sms = 148;
    cudaDeviceGetAttribute(&sms, cudaDevAttrMultiProcessorCount, 0);

    cudaFuncSetAttribute(k_fc1m, cudaFuncAttributeMaxDynamicSharedMemorySize, F1_SZ);
    cudaFuncSetAttribute(k2a,    cudaFuncAttributeMaxDynamicSharedMemorySize, K2A_SZ);
    cudaFuncSetAttribute(k2b,    cudaFuncAttributeMaxDynamicSharedMemorySize, K2B_SZ);
    cudaFuncSetAttribute(k_fc2m, cudaFuncAttributeMaxDynamicSharedMemorySize, F2_SZ);

    k_fc1m<<<NTF,   256, F1_SZ >>>(feat, fc1w, fc1b);
    k2a   <<<2*sms, 256, K2A_SZ>>>(xyz, knn, kxyz, d1w, d1b, d2w, d2b);
    k2b   <<<sms,   256, K2B_SZ>>>(g1w, g1b, g2w, g2b);
    k_soft<<<NP,    128        >>>(knn, out + RES_ELEMS);
    k_fc2m<<<NTF,   256, F2_SZ >>>(fc2w, fc2b, out);
}